// round 1
// baseline (speedup 1.0000x reference)
#include <cuda_runtime.h>

#define EMB   1024
#define NH    16
#define HD    64
#define BATCH 4
#define SEQ   2048
#define MROWS (BATCH*SEQ)   // 8192
#define KDIM  EMB           // 1024

// ---------------- scratch (static __device__, allocation-guard safe) ----------
__device__ float g_q [(size_t)BATCH*NH*SEQ*HD];   // [B,H,S,D] 32MB
__device__ float g_k [(size_t)BATCH*NH*SEQ*HD];
__device__ float g_v [(size_t)BATCH*NH*SEQ*HD];
__device__ float g_ao[(size_t)MROWS*EMB];         // attention out, [B,S,E] 32MB

// ---------------- GEMM: C = A[M,K] @ W[N,K]^T  (M=8192, N=1024, K=1024) -------
#define BM 128
#define BN 128
#define BK 16
#define AST 132          // padded row stride (k-major smem tiles)

template<bool SPLIT>
__global__ void __launch_bounds__(256, 2)
gemm_nt(const float* __restrict__ A, const float* __restrict__ W,
        float* __restrict__ C)
{
    __shared__ __align__(16) float As[BK * AST];
    __shared__ __align__(16) float Bs[BK * AST];

    const int tid = threadIdx.x;
    const int m0  = blockIdx.y * BM;
    const int n0  = blockIdx.x * BN;
    const int tr  = tid >> 4;         // 0..15  -> rows tr*8..tr*8+7
    const int tc  = tid & 15;         // 0..15  -> cols tc*8..tc*8+7

    float acc[8][8];
    #pragma unroll
    for (int i = 0; i < 8; i++)
        #pragma unroll
        for (int j = 0; j < 8; j++) acc[i][j] = 0.f;

    const int lrow = tid >> 2;        // 0..63
    const int lc4  = (tid & 3) * 4;   // 0,4,8,12

    for (int k0 = 0; k0 < KDIM; k0 += BK) {
        // A tile 128x16 -> As[k][m] (transposed), 2 float4 per thread
        #pragma unroll
        for (int p = 0; p < 2; p++) {
            int row = lrow + p * 64;
            float4 a4 = *(const float4*)(A + (size_t)(m0 + row) * KDIM + k0 + lc4);
            As[(lc4 + 0) * AST + row] = a4.x;
            As[(lc4 + 1) * AST + row] = a4.y;
            As[(lc4 + 2) * AST + row] = a4.z;
            As[(lc4 + 3) * AST + row] = a4.w;
        }
        // W tile 128x16 -> Bs[k][n]
        #pragma unroll
        for (int p = 0; p < 2; p++) {
            int row = lrow + p * 64;
            float4 b4 = *(const float4*)(W + (size_t)(n0 + row) * KDIM + k0 + lc4);
            Bs[(lc4 + 0) * AST + row] = b4.x;
            Bs[(lc4 + 1) * AST + row] = b4.y;
            Bs[(lc4 + 2) * AST + row] = b4.z;
            Bs[(lc4 + 3) * AST + row] = b4.w;
        }
        __syncthreads();

        #pragma unroll 4
        for (int kk = 0; kk < BK; kk++) {
            float a[8], b[8];
            float4 t;
            t = *(const float4*)&As[kk * AST + tr * 8 + 0];
            a[0]=t.x; a[1]=t.y; a[2]=t.z; a[3]=t.w;
            t = *(const float4*)&As[kk * AST + tr * 8 + 4];
            a[4]=t.x; a[5]=t.y; a[6]=t.z; a[7]=t.w;
            t = *(const float4*)&Bs[kk * AST + tc * 8 + 0];
            b[0]=t.x; b[1]=t.y; b[2]=t.z; b[3]=t.w;
            t = *(const float4*)&Bs[kk * AST + tc * 8 + 4];
            b[4]=t.x; b[5]=t.y; b[6]=t.z; b[7]=t.w;
            #pragma unroll
            for (int i = 0; i < 8; i++)
                #pragma unroll
                for (int j = 0; j < 8; j++)
                    acc[i][j] += a[i] * b[j];
        }
        __syncthreads();
    }

    // epilogue
    #pragma unroll
    for (int i = 0; i < 8; i++) {
        const int m = m0 + tr * 8 + i;
        #pragma unroll
        for (int j = 0; j < 8; j += 4) {
            const int n = n0 + tc * 8 + j;
            float4 v = make_float4(acc[i][j], acc[i][j+1], acc[i][j+2], acc[i][j+3]);
            size_t idx;
            if (SPLIT) {   // write [B,H,S,D]
                int b = m >> 11, s = m & 2047, h = n >> 6, d = n & 63;
                idx = ((size_t)(b * NH + h) * SEQ + s) * HD + d;
            } else {
                idx = (size_t)m * EMB + n;
            }
            *(float4*)(C + idx) = v;
        }
    }
}

// ---------------- causal flash attention (fp32) --------------------------------
// block = (bh, q-tile of 64 rows), 64 threads, 1 q-row per thread.
#define KST 68   // K/V tile row stride (16B aligned, reduces store conflicts)
#define SST 65   // score tile row stride (conflict-free scalar access)

__global__ void __launch_bounds__(64)
flash_attn(const float* __restrict__ Qg, const float* __restrict__ Kg,
           const float* __restrict__ Vg, const int* __restrict__ maskg,
           float* __restrict__ Og)
{
    __shared__ __align__(16) float KV[64 * KST];   // holds K tile, then V tile
    __shared__ float Ss[64 * SST];
    __shared__ int   msk[64];

    const int bh  = blockIdx.x;
    const int qt  = gridDim.y - 1 - blockIdx.y;    // heavy tiles first
    const int b   = bh >> 4;
    const int h   = bh & 15;
    const int tid = threadIdx.x;
    const int q0  = qt * 64;
    const int q_row = q0 + tid;
    const float NINF = __int_as_float(0xff800000);

    // q row in registers, pre-scaled by 1/sqrt(64)
    float q[HD];
    {
        const float* qp = Qg + ((size_t)bh * SEQ + q_row) * HD;
        #pragma unroll
        for (int d = 0; d < HD; d += 4) {
            float4 t = *(const float4*)(qp + d);
            q[d]   = t.x * 0.125f; q[d+1] = t.y * 0.125f;
            q[d+2] = t.z * 0.125f; q[d+3] = t.w * 0.125f;
        }
    }
    float acc[HD];
    #pragma unroll
    for (int d = 0; d < HD; d++) acc[d] = 0.f;
    float mrun = -1e30f, l = 0.f;

    const int* mrow = maskg + b * SEQ;

    for (int kt = 0; kt <= qt; kt++) {
        const int kv0 = kt * 64;
        __syncthreads();  // previous iteration finished reading KV (as V)

        // load K tile row tid + mask
        {
            const float* kp = Kg + ((size_t)bh * SEQ + kv0 + tid) * HD;
            #pragma unroll
            for (int d = 0; d < HD; d += 4) {
                float4 t = *(const float4*)(kp + d);
                KV[tid * KST + d]     = t.x;
                KV[tid * KST + d + 1] = t.y;
                KV[tid * KST + d + 2] = t.z;
                KV[tid * KST + d + 3] = t.w;
            }
            msk[tid] = mrow[kv0 + tid];
        }
        __syncthreads();

        // scores: s_j = q . k_j  (broadcast smem reads)
        float mloc = NINF;
        for (int j = 0; j < 64; j++) {
            const float* kr = &KV[j * KST];
            float s0 = 0.f, s1 = 0.f, s2 = 0.f, s3 = 0.f;
            #pragma unroll
            for (int d = 0; d < HD; d += 4) {
                float4 k4 = *(const float4*)(kr + d);
                s0 += q[d]   * k4.x;  s1 += q[d+1] * k4.y;
                s2 += q[d+2] * k4.z;  s3 += q[d+3] * k4.w;
            }
            float s = (s0 + s1) + (s2 + s3);
            if ((msk[j] == 0) | (kv0 + j > q_row)) s = NINF;
            Ss[tid * SST + j] = s;
            mloc = fmaxf(mloc, s);
        }

        // online softmax rescale
        const float mnew = fmaxf(mrun, mloc);
        const float corr = __expf(mrun - mnew);
        l *= corr;
        #pragma unroll
        for (int d = 0; d < HD; d++) acc[d] *= corr;
        mrun = mnew;

        __syncthreads();  // done reading K tile

        // load V tile into the same buffer
        {
            const float* vp = Vg + ((size_t)bh * SEQ + kv0 + tid) * HD;
            #pragma unroll
            for (int d = 0; d < HD; d += 4) {
                float4 t = *(const float4*)(vp + d);
                KV[tid * KST + d]     = t.x;
                KV[tid * KST + d + 1] = t.y;
                KV[tid * KST + d + 2] = t.z;
                KV[tid * KST + d + 3] = t.w;
            }
        }
        __syncthreads();

        // accumulate: acc += p_j * v_j
        for (int j = 0; j < 64; j++) {
            const float p = __expf(Ss[tid * SST + j] - mrun);
            l += p;
            const float* vr = &KV[j * KST];
            #pragma unroll
            for (int d = 0; d < HD; d += 4) {
                float4 v4 = *(const float4*)(vr + d);
                acc[d]   += p * v4.x;  acc[d+1] += p * v4.y;
                acc[d+2] += p * v4.z;  acc[d+3] += p * v4.w;
            }
        }
    }

    // write [B,S,E] so the output projection is a plain GEMM
    const float inv = 1.f / l;
    float* op = Og + ((size_t)(b * SEQ + q_row)) * EMB + h * HD;
    #pragma unroll
    for (int d = 0; d < HD; d += 4) {
        float4 v = make_float4(acc[d] * inv, acc[d+1] * inv,
                               acc[d+2] * inv, acc[d+3] * inv);
        *(float4*)(op + d) = v;
    }
}

// ---------------- launch --------------------------------------------------------
extern "C" void kernel_launch(void* const* d_in, const int* in_sizes, int n_in,
                              void* d_out, int out_size)
{
    const float* x  = (const float*)d_in[0];
    const int*   am = (const int*)  d_in[1];
    const float* wq = (const float*)d_in[2];
    const float* wk = (const float*)d_in[3];
    const float* wv = (const float*)d_in[4];
    const float* wo = (const float*)d_in[5];
    float* out = (float*)d_out;

    float *pq, *pk, *pv, *pao;
    cudaGetSymbolAddress((void**)&pq,  g_q);
    cudaGetSymbolAddress((void**)&pk,  g_k);
    cudaGetSymbolAddress((void**)&pv,  g_v);
    cudaGetSymbolAddress((void**)&pao, g_ao);

    dim3 gg(EMB / BN, MROWS / BM);          // (8, 64)
    gemm_nt<true><<<gg, 256>>>(x, wq, pq);
    gemm_nt<true><<<gg, 256>>>(x, wk, pk);
    gemm_nt<true><<<gg, 256>>>(x, wv, pv);

    flash_attn<<<dim3(BATCH * NH, SEQ / 64), 64>>>(pq, pk, pv, am, pao);

    gemm_nt<false><<<gg, 256>>>(pao, wo, out);
}

// round 2
// speedup vs baseline: 1.5576x; 1.5576x over previous
#include <cuda_runtime.h>
#include <stdint.h>

#define EMB   1024
#define NH    16
#define HD    64
#define BATCH 4
#define SEQ   2048
#define MROWS (BATCH*SEQ)   // 8192
#define KDIM  EMB           // 1024

// ---------------- scratch (static __device__, allocation-guard safe) ----------
__device__ float g_q [(size_t)BATCH*NH*SEQ*HD];   // [B,H,S,D]
__device__ float g_k [(size_t)BATCH*NH*SEQ*HD];
__device__ float g_v [(size_t)BATCH*NH*SEQ*HD];
__device__ float g_ao[(size_t)MROWS*EMB];         // attention out, [B,S,E]

// ---------------- TF32 helpers -------------------------------------------------
__device__ __forceinline__ uint32_t f2tf32(float x) {
    uint32_t r;
    asm("cvt.rna.tf32.f32 %0, %1;" : "=r"(r) : "f"(x));
    return r;
}

__device__ __forceinline__ void mma_tf32(float& d0, float& d1, float& d2, float& d3,
                                         uint32_t a0, uint32_t a1, uint32_t a2, uint32_t a3,
                                         uint32_t b0, uint32_t b1)
{
    asm volatile(
        "mma.sync.aligned.m16n8k8.row.col.f32.tf32.tf32.f32 "
        "{%0,%1,%2,%3}, {%4,%5,%6,%7}, {%8,%9}, {%0,%1,%2,%3};"
        : "+f"(d0), "+f"(d1), "+f"(d2), "+f"(d3)
        : "r"(a0), "r"(a1), "r"(a2), "r"(a3), "r"(b0), "r"(b1));
}

// ---------------- TF32 tensor-core GEMM ----------------------------------------
// C[M,N] = A[M,K] @ W[N,K]^T.  M=8192, N=1024, K=1024.
// Block tile 128x128x32, 256 threads (8 warps as 2x4), warp tile 64x32.
#define BM 128
#define BN 128
#define BK 32
#define SST36 36   // smem row stride: bank = (4*row + k) % 32 -> conflict-free frags

template<bool SPLIT>
__global__ void __launch_bounds__(256)
gemm_tc(const float* __restrict__ A, const float* __restrict__ W,
        float* __restrict__ C)
{
    __shared__ __align__(16) float As[BM * SST36];   // As[m][k]
    __shared__ __align__(16) float Ws[BN * SST36];   // Ws[n][k]

    const int tid    = threadIdx.x;
    const int lane   = tid & 31;
    const int warp   = tid >> 5;
    const int warp_m = warp >> 2;           // 0..1
    const int warp_n = warp & 3;            // 0..3
    const int m0     = blockIdx.y * BM;
    const int n0     = blockIdx.x * BN;
    const int mw     = warp_m * 64;         // warp m offset in tile
    const int nw     = warp_n * 32;         // warp n offset in tile

    const int grp = lane >> 2;              // 0..7
    const int tig = lane & 3;               // 0..3

    float acc[4][4][4];                     // [mi][ni][c0..c3]
    #pragma unroll
    for (int i = 0; i < 4; i++)
        #pragma unroll
        for (int j = 0; j < 4; j++)
            #pragma unroll
            for (int c = 0; c < 4; c++) acc[i][j][c] = 0.f;

    // global load mapping: 128x32 tile = 1024 float4, 4 per thread
    float4 sa[4], sw[4];
    #pragma unroll
    for (int p = 0; p < 4; p++) {
        const int idx = tid + p * 256;
        const int row = idx >> 3;
        const int col = (idx & 7) * 4;
        sa[p] = *(const float4*)(A + (size_t)(m0 + row) * KDIM + col);
        sw[p] = *(const float4*)(W + (size_t)(n0 + row) * KDIM + col);
    }

    for (int k0 = 0; k0 < KDIM; k0 += BK) {
        // stage (with tf32 rounding) into smem
        #pragma unroll
        for (int p = 0; p < 4; p++) {
            const int idx = tid + p * 256;
            const int row = idx >> 3;
            const int col = (idx & 7) * 4;
            float* ap = &As[row * SST36 + col];
            ap[0] = __uint_as_float(f2tf32(sa[p].x));
            ap[1] = __uint_as_float(f2tf32(sa[p].y));
            ap[2] = __uint_as_float(f2tf32(sa[p].z));
            ap[3] = __uint_as_float(f2tf32(sa[p].w));
            float* wp = &Ws[row * SST36 + col];
            wp[0] = __uint_as_float(f2tf32(sw[p].x));
            wp[1] = __uint_as_float(f2tf32(sw[p].y));
            wp[2] = __uint_as_float(f2tf32(sw[p].z));
            wp[3] = __uint_as_float(f2tf32(sw[p].w));
        }
        __syncthreads();

        // prefetch next K-slab while computing this one
        if (k0 + BK < KDIM) {
            #pragma unroll
            for (int p = 0; p < 4; p++) {
                const int idx = tid + p * 256;
                const int row = idx >> 3;
                const int col = (idx & 7) * 4;
                sa[p] = *(const float4*)(A + (size_t)(m0 + row) * KDIM + k0 + BK + col);
                sw[p] = *(const float4*)(W + (size_t)(n0 + row) * KDIM + k0 + BK + col);
            }
        }

        #pragma unroll
        for (int ks = 0; ks < BK / 8; ks++) {
            const int k8 = ks * 8;
            uint32_t af[4][4];
            #pragma unroll
            for (int mi = 0; mi < 4; mi++) {
                const int r0 = mw + mi * 16 + grp;
                af[mi][0] = __float_as_uint(As[(r0    ) * SST36 + k8 + tig    ]);
                af[mi][1] = __float_as_uint(As[(r0 + 8) * SST36 + k8 + tig    ]);
                af[mi][2] = __float_as_uint(As[(r0    ) * SST36 + k8 + tig + 4]);
                af[mi][3] = __float_as_uint(As[(r0 + 8) * SST36 + k8 + tig + 4]);
            }
            uint32_t bf[4][2];
            #pragma unroll
            for (int ni = 0; ni < 4; ni++) {
                const int nr = nw + ni * 8 + grp;
                bf[ni][0] = __float_as_uint(Ws[nr * SST36 + k8 + tig    ]);
                bf[ni][1] = __float_as_uint(Ws[nr * SST36 + k8 + tig + 4]);
            }
            #pragma unroll
            for (int mi = 0; mi < 4; mi++)
                #pragma unroll
                for (int ni = 0; ni < 4; ni++)
                    mma_tf32(acc[mi][ni][0], acc[mi][ni][1], acc[mi][ni][2], acc[mi][ni][3],
                             af[mi][0], af[mi][1], af[mi][2], af[mi][3],
                             bf[ni][0], bf[ni][1]);
        }
        __syncthreads();
    }

    // epilogue: c0,c1 at (row, 2*tig), (row, 2*tig+1); c2,c3 at row+8
    #pragma unroll
    for (int mi = 0; mi < 4; mi++) {
        #pragma unroll
        for (int ni = 0; ni < 4; ni++) {
            const int row = m0 + mw + mi * 16 + grp;
            const int col = n0 + nw + ni * 8 + 2 * tig;
            #pragma unroll
            for (int half = 0; half < 2; half++) {
                const int m = row + half * 8;
                const float v0 = acc[mi][ni][half * 2 + 0];
                const float v1 = acc[mi][ni][half * 2 + 1];
                size_t idx;
                if (SPLIT) {   // [B,H,S,D]
                    const int b = m >> 11, s = m & 2047, h = col >> 6, d = col & 63;
                    idx = ((size_t)(b * NH + h) * SEQ + s) * HD + d;
                } else {
                    idx = (size_t)m * EMB + col;
                }
                *(float2*)(C + idx) = make_float2(v0, v1);
            }
        }
    }
}

// ---------------- causal flash attention (fp32) --------------------------------
// block = (bh, q-tile of 64 rows), 64 threads, 1 q-row per thread.
#define KST 68
#define SSTA 65

__global__ void __launch_bounds__(64)
flash_attn(const float* __restrict__ Qg, const float* __restrict__ Kg,
           const float* __restrict__ Vg, const int* __restrict__ maskg,
           float* __restrict__ Og)
{
    __shared__ __align__(16) float KV[64 * KST];
    __shared__ float Ss[64 * SSTA];
    __shared__ int   msk[64];

    const int bh  = blockIdx.x;
    const int qt  = gridDim.y - 1 - blockIdx.y;    // heavy tiles first
    const int b   = bh >> 4;
    const int h   = bh & 15;
    const int tid = threadIdx.x;
    const int q0  = qt * 64;
    const int q_row = q0 + tid;
    const float NINF = __int_as_float(0xff800000);

    float q[HD];
    {
        const float* qp = Qg + ((size_t)bh * SEQ + q_row) * HD;
        #pragma unroll
        for (int d = 0; d < HD; d += 4) {
            float4 t = *(const float4*)(qp + d);
            q[d]   = t.x * 0.125f; q[d+1] = t.y * 0.125f;
            q[d+2] = t.z * 0.125f; q[d+3] = t.w * 0.125f;
        }
    }
    float acc[HD];
    #pragma unroll
    for (int d = 0; d < HD; d++) acc[d] = 0.f;
    float mrun = -1e30f, l = 0.f;

    const int* mrow = maskg + b * SEQ;

    for (int kt = 0; kt <= qt; kt++) {
        const int kv0 = kt * 64;
        __syncthreads();

        {
            const float* kp = Kg + ((size_t)bh * SEQ + kv0 + tid) * HD;
            #pragma unroll
            for (int d = 0; d < HD; d += 4) {
                float4 t = *(const float4*)(kp + d);
                KV[tid * KST + d]     = t.x;
                KV[tid * KST + d + 1] = t.y;
                KV[tid * KST + d + 2] = t.z;
                KV[tid * KST + d + 3] = t.w;
            }
            msk[tid] = mrow[kv0 + tid];
        }
        __syncthreads();

        float mloc = NINF;
        for (int j = 0; j < 64; j++) {
            const float* kr = &KV[j * KST];
            float s0 = 0.f, s1 = 0.f, s2 = 0.f, s3 = 0.f;
            #pragma unroll
            for (int d = 0; d < HD; d += 4) {
                float4 k4 = *(const float4*)(kr + d);
                s0 += q[d]   * k4.x;  s1 += q[d+1] * k4.y;
                s2 += q[d+2] * k4.z;  s3 += q[d+3] * k4.w;
            }
            float s = (s0 + s1) + (s2 + s3);
            if ((msk[j] == 0) | (kv0 + j > q_row)) s = NINF;
            Ss[tid * SSTA + j] = s;
            mloc = fmaxf(mloc, s);
        }

        const float mnew = fmaxf(mrun, mloc);
        const float corr = __expf(mrun - mnew);
        l *= corr;
        #pragma unroll
        for (int d = 0; d < HD; d++) acc[d] *= corr;
        mrun = mnew;

        __syncthreads();

        {
            const float* vp = Vg + ((size_t)bh * SEQ + kv0 + tid) * HD;
            #pragma unroll
            for (int d = 0; d < HD; d += 4) {
                float4 t = *(const float4*)(vp + d);
                KV[tid * KST + d]     = t.x;
                KV[tid * KST + d + 1] = t.y;
                KV[tid * KST + d + 2] = t.z;
                KV[tid * KST + d + 3] = t.w;
            }
        }
        __syncthreads();

        for (int j = 0; j < 64; j++) {
            const float p = __expf(Ss[tid * SSTA + j] - mrun);
            l += p;
            const float* vr = &KV[j * KST];
            #pragma unroll
            for (int d = 0; d < HD; d += 4) {
                float4 v4 = *(const float4*)(vr + d);
                acc[d]   += p * v4.x;  acc[d+1] += p * v4.y;
                acc[d+2] += p * v4.z;  acc[d+3] += p * v4.w;
            }
        }
    }

    const float inv = 1.f / l;
    float* op = Og + ((size_t)(b * SEQ + q_row)) * EMB + h * HD;
    #pragma unroll
    for (int d = 0; d < HD; d += 4) {
        float4 v = make_float4(acc[d] * inv, acc[d+1] * inv,
                               acc[d+2] * inv, acc[d+3] * inv);
        *(float4*)(op + d) = v;
    }
}

// ---------------- launch --------------------------------------------------------
extern "C" void kernel_launch(void* const* d_in, const int* in_sizes, int n_in,
                              void* d_out, int out_size)
{
    const float* x  = (const float*)d_in[0];
    const int*   am = (const int*)  d_in[1];
    const float* wq = (const float*)d_in[2];
    const float* wk = (const float*)d_in[3];
    const float* wv = (const float*)d_in[4];
    const float* wo = (const float*)d_in[5];
    float* out = (float*)d_out;

    float *pq, *pk, *pv, *pao;
    cudaGetSymbolAddress((void**)&pq,  g_q);
    cudaGetSymbolAddress((void**)&pk,  g_k);
    cudaGetSymbolAddress((void**)&pv,  g_v);
    cudaGetSymbolAddress((void**)&pao, g_ao);

    dim3 gg(EMB / BN, MROWS / BM);          // (8, 64)
    gemm_tc<true><<<gg, 256>>>(x, wq, pq);
    gemm_tc<true><<<gg, 256>>>(x, wk, pk);
    gemm_tc<true><<<gg, 256>>>(x, wv, pv);

    flash_attn<<<dim3(BATCH * NH, SEQ / 64), 64>>>(pq, pk, pv, am, pao);

    gemm_tc<false><<<gg, 256>>>(pao, wo, out);
}

// round 6
// speedup vs baseline: 3.5341x; 2.2689x over previous
#include <cuda_runtime.h>
#include <stdint.h>

#define EMB   1024
#define NH    16
#define HD    64
#define BATCH 4
#define SEQ   2048
#define MROWS (BATCH*SEQ)   // 8192
#define KDIM  EMB           // 1024

// ---------------- scratch (static __device__, allocation-guard safe) ----------
__device__ float g_q [(size_t)BATCH*NH*SEQ*HD];   // [B,H,S,D]
__device__ float g_k [(size_t)BATCH*NH*SEQ*HD];
__device__ float g_v [(size_t)BATCH*NH*SEQ*HD];
__device__ float g_ao[(size_t)MROWS*EMB];         // attention out, [B,S,E]

// ---------------- TF32 helpers -------------------------------------------------
__device__ __forceinline__ uint32_t f2tf32(float x) {
    uint32_t r;
    asm("cvt.rna.tf32.f32 %0, %1;" : "=r"(r) : "f"(x));
    return r;
}

__device__ __forceinline__ void mma_tf32(float& d0, float& d1, float& d2, float& d3,
                                         uint32_t a0, uint32_t a1, uint32_t a2, uint32_t a3,
                                         uint32_t b0, uint32_t b1)
{
    asm volatile(
        "mma.sync.aligned.m16n8k8.row.col.f32.tf32.tf32.f32 "
        "{%0,%1,%2,%3}, {%4,%5,%6,%7}, {%8,%9}, {%0,%1,%2,%3};"
        : "+f"(d0), "+f"(d1), "+f"(d2), "+f"(d3)
        : "r"(a0), "r"(a1), "r"(a2), "r"(a3), "r"(b0), "r"(b1));
}

// ---------------- TF32 tensor-core GEMM ----------------------------------------
// C[M,N] = A[M,K] @ W[N,K]^T.  M=8192, N=1024, K=1024.
#define BM 128
#define BN 128
#define BK 32
#define SST36 36

template<bool SPLIT>
__global__ void __launch_bounds__(256)
gemm_tc(const float* __restrict__ A, const float* __restrict__ W,
        float* __restrict__ C)
{
    __shared__ __align__(16) float As[BM * SST36];
    __shared__ __align__(16) float Ws[BN * SST36];

    const int tid    = threadIdx.x;
    const int lane   = tid & 31;
    const int warp   = tid >> 5;
    const int warp_m = warp >> 2;
    const int warp_n = warp & 3;
    const int m0     = blockIdx.y * BM;
    const int n0     = blockIdx.x * BN;
    const int mw     = warp_m * 64;
    const int nw     = warp_n * 32;

    const int grp = lane >> 2;
    const int tig = lane & 3;

    float acc[4][4][4];
    #pragma unroll
    for (int i = 0; i < 4; i++)
        #pragma unroll
        for (int j = 0; j < 4; j++)
            #pragma unroll
            for (int c = 0; c < 4; c++) acc[i][j][c] = 0.f;

    float4 sa[4], sw[4];
    #pragma unroll
    for (int p = 0; p < 4; p++) {
        const int idx = tid + p * 256;
        const int row = idx >> 3;
        const int col = (idx & 7) * 4;
        sa[p] = *(const float4*)(A + (size_t)(m0 + row) * KDIM + col);
        sw[p] = *(const float4*)(W + (size_t)(n0 + row) * KDIM + col);
    }

    for (int k0 = 0; k0 < KDIM; k0 += BK) {
        #pragma unroll
        for (int p = 0; p < 4; p++) {
            const int idx = tid + p * 256;
            const int row = idx >> 3;
            const int col = (idx & 7) * 4;
            float* ap = &As[row * SST36 + col];
            ap[0] = __uint_as_float(f2tf32(sa[p].x));
            ap[1] = __uint_as_float(f2tf32(sa[p].y));
            ap[2] = __uint_as_float(f2tf32(sa[p].z));
            ap[3] = __uint_as_float(f2tf32(sa[p].w));
            float* wp = &Ws[row * SST36 + col];
            wp[0] = __uint_as_float(f2tf32(sw[p].x));
            wp[1] = __uint_as_float(f2tf32(sw[p].y));
            wp[2] = __uint_as_float(f2tf32(sw[p].z));
            wp[3] = __uint_as_float(f2tf32(sw[p].w));
        }
        __syncthreads();

        if (k0 + BK < KDIM) {
            #pragma unroll
            for (int p = 0; p < 4; p++) {
                const int idx = tid + p * 256;
                const int row = idx >> 3;
                const int col = (idx & 7) * 4;
                sa[p] = *(const float4*)(A + (size_t)(m0 + row) * KDIM + k0 + BK + col);
                sw[p] = *(const float4*)(W + (size_t)(n0 + row) * KDIM + k0 + BK + col);
            }
        }

        #pragma unroll
        for (int ks = 0; ks < BK / 8; ks++) {
            const int k8 = ks * 8;
            uint32_t af[4][4];
            #pragma unroll
            for (int mi = 0; mi < 4; mi++) {
                const int r0 = mw + mi * 16 + grp;
                af[mi][0] = __float_as_uint(As[(r0    ) * SST36 + k8 + tig    ]);
                af[mi][1] = __float_as_uint(As[(r0 + 8) * SST36 + k8 + tig    ]);
                af[mi][2] = __float_as_uint(As[(r0    ) * SST36 + k8 + tig + 4]);
                af[mi][3] = __float_as_uint(As[(r0 + 8) * SST36 + k8 + tig + 4]);
            }
            uint32_t bf[4][2];
            #pragma unroll
            for (int ni = 0; ni < 4; ni++) {
                const int nr = nw + ni * 8 + grp;
                bf[ni][0] = __float_as_uint(Ws[nr * SST36 + k8 + tig    ]);
                bf[ni][1] = __float_as_uint(Ws[nr * SST36 + k8 + tig + 4]);
            }
            #pragma unroll
            for (int mi = 0; mi < 4; mi++)
                #pragma unroll
                for (int ni = 0; ni < 4; ni++)
                    mma_tf32(acc[mi][ni][0], acc[mi][ni][1], acc[mi][ni][2], acc[mi][ni][3],
                             af[mi][0], af[mi][1], af[mi][2], af[mi][3],
                             bf[ni][0], bf[ni][1]);
        }
        __syncthreads();
    }

    #pragma unroll
    for (int mi = 0; mi < 4; mi++) {
        #pragma unroll
        for (int ni = 0; ni < 4; ni++) {
            const int row = m0 + mw + mi * 16 + grp;
            const int col = n0 + nw + ni * 8 + 2 * tig;
            #pragma unroll
            for (int half = 0; half < 2; half++) {
                const int m = row + half * 8;
                const float v0 = acc[mi][ni][half * 2 + 0];
                const float v1 = acc[mi][ni][half * 2 + 1];
                size_t idx;
                if (SPLIT) {
                    const int b = m >> 11, s = m & 2047, h = col >> 6, d = col & 63;
                    idx = ((size_t)(b * NH + h) * SEQ + s) * HD + d;
                } else {
                    idx = (size_t)m * EMB + col;
                }
                *(float2*)(C + idx) = make_float2(v0, v1);
            }
        }
    }
}

// ---------------- tensor-core causal flash attention ---------------------------
// CTA: 128 q-rows of one (b,h). 8 warps x 16 q-rows. KV tiles of 64.
#define KSTR 68     // K / P / Q smem stride  -> bank = (4*row + col) % 32
#define VSTR 72     // V smem stride          -> bank = (8*row + col) % 32

#define FLASH_SMEM_FLOATS (64*KSTR + 64*VSTR + 128*KSTR)
#define FLASH_SMEM_BYTES  (FLASH_SMEM_FLOATS*4 + 64*4)

__global__ void __launch_bounds__(256)
flash_tc(const float* __restrict__ Qg, const float* __restrict__ Kg,
         const float* __restrict__ Vg, const int* __restrict__ maskg,
         float* __restrict__ Og)
{
    extern __shared__ __align__(16) float sm[];
    float* Ks = sm;                    // [64][KSTR]
    float* Vs = Ks + 64 * KSTR;        // [64][VSTR]
    float* Ps = Vs + 64 * VSTR;        // [128][KSTR]  (Q staging, then P)
    int*   msk = (int*)(Ps + 128 * KSTR);

    const int bh   = blockIdx.x;
    const int b    = bh >> 4;
    const int h    = bh & 15;
    const int qt   = gridDim.y - 1 - blockIdx.y;   // heavy tiles first
    const int q0   = qt * 128;
    const int tid  = threadIdx.x;
    const int lane = tid & 31;
    const int warp = tid >> 5;
    const int grp  = lane >> 2;        // 0..7
    const int tig  = lane & 3;         // 0..3
    const int mw   = warp * 16;        // warp's q-row offset in tile

    const float qscale = 0.125f * 1.44269504088896f;  // 1/sqrt(64) * log2(e)

    // ---- stage Q tile [128 x 64] (scaled, tf32) into Ps, pull fragments -------
    #pragma unroll
    for (int p = 0; p < 8; p++) {
        const int idx = tid + p * 256;
        const int row = idx >> 4;
        const int col = (idx & 15) * 4;
        float4 t = *(const float4*)(Qg + ((size_t)bh * SEQ + q0 + row) * HD + col);
        float* dp = &Ps[row * KSTR + col];
        dp[0] = __uint_as_float(f2tf32(t.x * qscale));
        dp[1] = __uint_as_float(f2tf32(t.y * qscale));
        dp[2] = __uint_as_float(f2tf32(t.z * qscale));
        dp[3] = __uint_as_float(f2tf32(t.w * qscale));
    }
    __syncthreads();

    uint32_t qf[8][4];
    #pragma unroll
    for (int ks = 0; ks < 8; ks++) {
        const int k8 = ks * 8;
        qf[ks][0] = __float_as_uint(Ps[(mw + grp    ) * KSTR + k8 + tig    ]);
        qf[ks][1] = __float_as_uint(Ps[(mw + grp + 8) * KSTR + k8 + tig    ]);
        qf[ks][2] = __float_as_uint(Ps[(mw + grp    ) * KSTR + k8 + tig + 4]);
        qf[ks][3] = __float_as_uint(Ps[(mw + grp + 8) * KSTR + k8 + tig + 4]);
    }

    float o[8][4];
    #pragma unroll
    for (int nt = 0; nt < 8; nt++)
        #pragma unroll
        for (int c = 0; c < 4; c++) o[nt][c] = 0.f;
    float m0r = -1e30f, m1r = -1e30f, l0 = 0.f, l1 = 0.f;

    const int q_row0 = q0 + mw + grp;
    const int q_row1 = q_row0 + 8;
    const int* mrow  = maskg + b * SEQ;
    const int  ntile = 2 * qt + 2;     // causal: kv tiles 0 .. 2*qt+1

    for (int kt = 0; kt < ntile; kt++) {
        const int kv0 = kt * 64;
        __syncthreads();   // previous tile's Ks/Vs reads (and P reads) complete

        // ---- load K,V tiles (tf32) + mask ----
        #pragma unroll
        for (int p = 0; p < 4; p++) {
            const int idx = tid + p * 256;
            const int row = idx >> 4;
            const int col = (idx & 15) * 4;
            float4 tk = *(const float4*)(Kg + ((size_t)bh * SEQ + kv0 + row) * HD + col);
            float* kp = &Ks[row * KSTR + col];
            kp[0] = __uint_as_float(f2tf32(tk.x));
            kp[1] = __uint_as_float(f2tf32(tk.y));
            kp[2] = __uint_as_float(f2tf32(tk.z));
            kp[3] = __uint_as_float(f2tf32(tk.w));
            float4 tv = *(const float4*)(Vg + ((size_t)bh * SEQ + kv0 + row) * HD + col);
            float* vp = &Vs[row * VSTR + col];
            vp[0] = __uint_as_float(f2tf32(tv.x));
            vp[1] = __uint_as_float(f2tf32(tv.y));
            vp[2] = __uint_as_float(f2tf32(tv.z));
            vp[3] = __uint_as_float(f2tf32(tv.w));
        }
        if (tid < 64) msk[tid] = mrow[kv0 + tid];
        __syncthreads();

        // ---- S = Q @ K^T  (scores already in log2 domain via qscale) ----
        float s[8][4];
        #pragma unroll
        for (int nt = 0; nt < 8; nt++)
            #pragma unroll
            for (int c = 0; c < 4; c++) s[nt][c] = 0.f;

        #pragma unroll
        for (int ks = 0; ks < 8; ks++) {
            const int k8 = ks * 8;
            #pragma unroll
            for (int nt = 0; nt < 8; nt++) {
                const uint32_t b0 = __float_as_uint(Ks[(nt * 8 + grp) * KSTR + k8 + tig    ]);
                const uint32_t b1 = __float_as_uint(Ks[(nt * 8 + grp) * KSTR + k8 + tig + 4]);
                mma_tf32(s[nt][0], s[nt][1], s[nt][2], s[nt][3],
                         qf[ks][0], qf[ks][1], qf[ks][2], qf[ks][3], b0, b1);
            }
        }

        // ---- mask + online softmax ----
        float mx0 = -1e30f, mx1 = -1e30f;
        #pragma unroll
        for (int nt = 0; nt < 8; nt++) {
            const int lc0 = nt * 8 + 2 * tig;
            const int c0g = kv0 + lc0;
            const bool v0 = (msk[lc0] != 0);
            const bool v1 = (msk[lc0 + 1] != 0);
            if (!v0 | (c0g     > q_row0)) s[nt][0] = -1e30f;
            if (!v1 | (c0g + 1 > q_row0)) s[nt][1] = -1e30f;
            if (!v0 | (c0g     > q_row1)) s[nt][2] = -1e30f;
            if (!v1 | (c0g + 1 > q_row1)) s[nt][3] = -1e30f;
            mx0 = fmaxf(mx0, fmaxf(s[nt][0], s[nt][1]));
            mx1 = fmaxf(mx1, fmaxf(s[nt][2], s[nt][3]));
        }
        mx0 = fmaxf(mx0, __shfl_xor_sync(0xffffffffu, mx0, 1));
        mx0 = fmaxf(mx0, __shfl_xor_sync(0xffffffffu, mx0, 2));
        mx1 = fmaxf(mx1, __shfl_xor_sync(0xffffffffu, mx1, 1));
        mx1 = fmaxf(mx1, __shfl_xor_sync(0xffffffffu, mx1, 2));

        const float mn0 = fmaxf(m0r, mx0);
        const float mn1 = fmaxf(m1r, mx1);
        const float cr0 = exp2f(m0r - mn0);
        const float cr1 = exp2f(m1r - mn1);
        l0 *= cr0;  l1 *= cr1;
        m0r = mn0;  m1r = mn1;
        #pragma unroll
        for (int nt = 0; nt < 8; nt++) {
            o[nt][0] *= cr0; o[nt][1] *= cr0;
            o[nt][2] *= cr1; o[nt][3] *= cr1;
        }

        // ---- p = exp2(s - m); store P slice to smem in tf32 ----
        #pragma unroll
        for (int nt = 0; nt < 8; nt++) {
            const float p0 = exp2f(s[nt][0] - mn0);
            const float p1 = exp2f(s[nt][1] - mn0);
            const float p2 = exp2f(s[nt][2] - mn1);
            const float p3 = exp2f(s[nt][3] - mn1);
            l0 += p0 + p1;
            l1 += p2 + p3;
            const int col = nt * 8 + 2 * tig;
            float* pr0 = &Ps[(mw + grp    ) * KSTR + col];
            float* pr1 = &Ps[(mw + grp + 8) * KSTR + col];
            pr0[0] = __uint_as_float(f2tf32(p0));
            pr0[1] = __uint_as_float(f2tf32(p1));
            pr1[0] = __uint_as_float(f2tf32(p2));
            pr1[1] = __uint_as_float(f2tf32(p3));
        }
        __syncwarp();

        // ---- O += P @ V ----
        #pragma unroll
        for (int ks = 0; ks < 8; ks++) {
            const int k8 = ks * 8;
            uint32_t a0 = __float_as_uint(Ps[(mw + grp    ) * KSTR + k8 + tig    ]);
            uint32_t a1 = __float_as_uint(Ps[(mw + grp + 8) * KSTR + k8 + tig    ]);
            uint32_t a2 = __float_as_uint(Ps[(mw + grp    ) * KSTR + k8 + tig + 4]);
            uint32_t a3 = __float_as_uint(Ps[(mw + grp + 8) * KSTR + k8 + tig + 4]);
            #pragma unroll
            for (int nt = 0; nt < 8; nt++) {
                const uint32_t b0 = __float_as_uint(Vs[(k8 + tig    ) * VSTR + nt * 8 + grp]);
                const uint32_t b1 = __float_as_uint(Vs[(k8 + tig + 4) * VSTR + nt * 8 + grp]);
                mma_tf32(o[nt][0], o[nt][1], o[nt][2], o[nt][3],
                         a0, a1, a2, a3, b0, b1);
            }
        }
    }

    // ---- finalize: l reduce + normalize + store ----
    l0 += __shfl_xor_sync(0xffffffffu, l0, 1);
    l0 += __shfl_xor_sync(0xffffffffu, l0, 2);
    l1 += __shfl_xor_sync(0xffffffffu, l1, 1);
    l1 += __shfl_xor_sync(0xffffffffu, l1, 2);
    const float inv0 = 1.f / l0;
    const float inv1 = 1.f / l1;

    float* o0 = Og + ((size_t)(b * SEQ + q_row0)) * EMB + h * HD;
    float* o1 = Og + ((size_t)(b * SEQ + q_row1)) * EMB + h * HD;
    #pragma unroll
    for (int nt = 0; nt < 8; nt++) {
        const int col = nt * 8 + 2 * tig;
        *(float2*)(o0 + col) = make_float2(o[nt][0] * inv0, o[nt][1] * inv0);
        *(float2*)(o1 + col) = make_float2(o[nt][2] * inv1, o[nt][3] * inv1);
    }
}

// ---------------- launch --------------------------------------------------------
extern "C" void kernel_launch(void* const* d_in, const int* in_sizes, int n_in,
                              void* d_out, int out_size)
{
    const float* x  = (const float*)d_in[0];
    const int*   am = (const int*)  d_in[1];
    const float* wq = (const float*)d_in[2];
    const float* wk = (const float*)d_in[3];
    const float* wv = (const float*)d_in[4];
    const float* wo = (const float*)d_in[5];
    float* out = (float*)d_out;

    float *pq, *pk, *pv, *pao;
    cudaGetSymbolAddress((void**)&pq,  g_q);
    cudaGetSymbolAddress((void**)&pk,  g_k);
    cudaGetSymbolAddress((void**)&pv,  g_v);
    cudaGetSymbolAddress((void**)&pao, g_ao);

    dim3 gg(EMB / BN, MROWS / BM);          // (8, 64)
    gemm_tc<true><<<gg, 256>>>(x, wq, pq);
    gemm_tc<true><<<gg, 256>>>(x, wk, pk);
    gemm_tc<true><<<gg, 256>>>(x, wv, pv);

    // unconditional (no static guards — harness requires identical behavior
    // on every call); host-side attribute set, graph-capture safe.
    cudaFuncSetAttribute(flash_tc, cudaFuncAttributeMaxDynamicSharedMemorySize,
                         FLASH_SMEM_BYTES);
    flash_tc<<<dim3(BATCH * NH, SEQ / 128), 256, FLASH_SMEM_BYTES>>>(pq, pk, pv, am, pao);

    gemm_tc<false><<<gg, 256>>>(pao, wo, out);
}